// round 2
// baseline (speedup 1.0000x reference)
#include <cuda_runtime.h>
#include <cstdint>

#define CCH 64
#define HH 128
#define WW 128
#define NBATCH 32
#define KW 7
#define XS_STRIDE 152   // >= 146, multiple of 4 (float4 alignment not needed but keep tidy)
#define NTHREADS 256

// smem layout: Ws[7][64][64] (weights transposed, co contiguous) then xs[64][XS_STRIDE]
#define WS_ELEMS (KW * CCH * CCH)      // 28672 floats = 114688 B
#define XS_ELEMS (CCH * XS_STRIDE)     // 9728  floats = 38912 B
#define SMEM_BYTES ((WS_ELEMS + XS_ELEMS) * 4)

__device__ __forceinline__ void ffma2(unsigned long long& d,
                                      unsigned long long a,
                                      unsigned long long b) {
    asm("fma.rn.f32x2 %0, %1, %2, %0;" : "+l"(d) : "l"(a), "l"(b));
}

__device__ __forceinline__ unsigned long long pack_dup(float x) {
    unsigned long long r;
    asm("mov.b64 %0, {%1, %1};" : "=l"(r) : "f"(x));
    return r;
}

__device__ __forceinline__ void unpack2(unsigned long long v, float& lo, float& hi) {
    asm("mov.b64 {%0, %1}, %2;" : "=f"(lo), "=f"(hi) : "l"(v));
}

extern "C" __global__ void __launch_bounds__(NTHREADS, 1)
fused_conv_roll_kernel(const float* __restrict__ x,
                       const float* __restrict__ wconv,
                       const float* __restrict__ p4,
                       float* __restrict__ out) {
    extern __shared__ float smem[];
    float* Ws = smem;                  // [j][ci][co]
    float* xs = smem + WS_ELEMS;       // [ci][col], col = w + 9, w in [-9, 136]

    const int tid = threadIdx.x;

    // Load + transpose weights once per (persistent) block.
    // global layout: wconv[co][ci][0][j], idx = (co*64 + ci)*7 + j
    for (int idx = tid; idx < WS_ELEMS; idx += NTHREADS) {
        int co  = idx / (CCH * KW);
        int rem = idx - co * (CCH * KW);
        int ci  = rem / KW;
        int j   = rem - ci * KW;
        Ws[(j * CCH + ci) * CCH + co] = wconv[idx];
    }
    const float p40 = p4[0], p41 = p4[1], p42 = p4[2];

    const int tw  = tid & 15;     // 16 threads along w
    const int tco = tid >> 4;     // 16 threads along co
    const int co0 = tco * 4;

    const int total_rows = NBATCH * HH;

    for (int row = blockIdx.x; row < total_rows; row += gridDim.x) {
        const int n = row >> 7;          // H == 128
        const int h = row & (HH - 1);

        __syncthreads();  // previous iteration's epilogue reads of xs are done

        // Stage x[n][:, h, :] into smem with +/-9 zero padding along w
        {
            const float* xrow = x + ((size_t)(n * CCH) * HH + h) * WW;
            for (int idx = tid; idx < CCH * 146; idx += NTHREADS) {
                int ci  = idx / 146;
                int col = idx - ci * 146;
                int w   = col - 9;
                float v = (w >= 0 && w < WW) ? xrow[(size_t)ci * (HH * WW) + w] : 0.0f;
                xs[ci * XS_STRIDE + col] = v;
            }
        }
        __syncthreads();

        // acc2[cp][e]: packed pair of channels (co0+2cp, co0+2cp+1), w = tw + 16*e
        unsigned long long acc2[2][8];
        #pragma unroll
        for (int cp = 0; cp < 2; ++cp)
            #pragma unroll
            for (int e = 0; e < 8; ++e) acc2[cp][e] = 0ULL;

        #pragma unroll
        for (int j = 0; j < KW; ++j) {
            const float* wsj = Ws + j * CCH * CCH;
            // needed x col for output w, tap j: w + 3j - 9 -> storage col w + 3j
            const float* xsb = xs + tw + 3 * j;
            #pragma unroll 4
            for (int ci = 0; ci < CCH; ++ci) {
                // two packed weight pairs: (w[co0],w[co0+1]) (w[co0+2],w[co0+3])
                const ulonglong2 wv =
                    *(const ulonglong2*)(wsj + ci * CCH + co0);
                const float* xr = xsb + ci * XS_STRIDE;
                #pragma unroll
                for (int e = 0; e < 8; ++e) {
                    unsigned long long xp = pack_dup(xr[16 * e]);
                    ffma2(acc2[0][e], wv.x, xp);
                    ffma2(acc2[1][e], wv.y, xp);
                }
            }
        }

        // Epilogue: out = (x + t3) * t4
        // t4[h][w] = sum_k p4[k] * x[(h-1 mod H) + 2k - 2][(w+2) mod W], rows zero-padded
        const int hm1 = (h - 1 + HH) & (HH - 1);
        const int r0 = hm1 - 2, r1 = hm1, r2 = hm1 + 2;
        const bool v0 = (r0 >= 0);
        const bool v2 = (r2 < HH);
        const float* xn = x + (size_t)n * CCH * HH * WW;
        float* outn = out + (size_t)n * CCH * HH * WW;

        #pragma unroll
        for (int cp = 0; cp < 2; ++cp) {
            #pragma unroll
            for (int half = 0; half < 2; ++half) {
                const int co = co0 + 2 * cp + half;
                const float* xc = xn + (size_t)co * HH * WW;
                float* oc = outn + ((size_t)co * HH + h) * WW;
                #pragma unroll
                for (int e = 0; e < 8; ++e) {
                    const int w  = tw + 16 * e;
                    const int wp = (w + 2) & (WW - 1);
                    float t4 = p41 * xc[r1 * WW + wp];
                    if (v0) t4 = fmaf(p40, xc[r0 * WW + wp], t4);
                    if (v2) t4 = fmaf(p42, xc[r2 * WW + wp], t4);
                    float lo, hi;
                    unpack2(acc2[cp][e], lo, hi);
                    const float t3 = half ? hi : lo;
                    const float xval = xs[co * XS_STRIDE + w + 9];
                    oc[w] = (xval + t3) * t4;
                }
            }
        }
    }
}

extern "C" void kernel_launch(void* const* d_in, const int* in_sizes, int n_in,
                              void* d_out, int out_size) {
    const float* x     = (const float*)d_in[0];
    const float* wconv = (const float*)d_in[1];
    const float* p4    = (const float*)d_in[2];
    float* out         = (float*)d_out;

    (void)in_sizes; (void)n_in; (void)out_size;

    cudaFuncSetAttribute(fused_conv_roll_kernel,
                         cudaFuncAttributeMaxDynamicSharedMemorySize, SMEM_BYTES);

    int dev = 0, sms = 148;
    cudaGetDevice(&dev);
    cudaDeviceGetAttribute(&sms, cudaDevAttrMultiProcessorCount, dev);

    fused_conv_roll_kernel<<<sms, NTHREADS, SMEM_BYTES>>>(x, wconv, p4, out);
}